// round 10
// baseline (speedup 1.0000x reference)
#include <cuda_runtime.h>
#include <cuda_fp16.h>
#include <cstdint>

// Warp-specialized pipeline: producer warps 4-7 run conv1 (FFMA2) into a
// double-buffered smem fp16 tile; consumer warps 0-3 run conv2 (HMMA,
// m64n64 per warp) + epilogue. 9 tiles per CTA, 1 CTA/SM, named barriers.
// Full-image equivalence of the tile/crop/stitch pipeline (pad lo=0, hi=1).

#define IMG 2304
#define H2  576

typedef unsigned long long u64;

__device__ __half g_w2t[9 * 128 * 64];   // [kk][n=co][k=ci] fp16, SW128-baked
__device__ u64    g_w1d[27 * 64];        // conv1 weights dup-packed (w,w)

// smem map (bytes)
#define BUFSZ   71808                // one IN tile: E 36992 + O 34816
#define INO_REL 36992
#define B_OFF   143616               // B dbuf 2 x 16384
#define W1_OFF  176384               // 13824
#define IMG_OFF 190208               // 3ch x 19rows x 108 f32 = 24624
#define SMEMT   214832
#define IROW    108                  // E[0..35] | O@36 | S@72
#define IPLANE  (19 * IROW)

// named barrier ids
#define FULL_ID(b)  (1 + (b))
#define EMPTY_ID(b) (3 + (b))
#define PBAR_ID 5
#define CBAR_ID 6
#define BAR_SYNC(id, cnt) \
    asm volatile("bar.sync %0, %1;" :: "r"(id), "r"(cnt) : "memory")
#define BAR_ARRIVE(id, cnt) \
    asm volatile("bar.arrive %0, %1;" :: "r"(id), "r"(cnt) : "memory")
#define MEMBAR_CTA() asm volatile("membar.cta;" ::: "memory")

// ---------------- helpers ----------------
__device__ __forceinline__ u64 pk2(float x, float y) {
    u64 r; asm("mov.b64 %0, {%1, %2};" : "=l"(r) : "f"(x), "f"(y)); return r;
}
__device__ __forceinline__ void upk2(u64 v, float& x, float& y) {
    asm("mov.b64 {%0, %1}, %2;" : "=f"(x), "=f"(y) : "l"(v));
}
__device__ __forceinline__ void fma2(u64& d, u64 a, u64 b) {
    asm("fma.rn.f32x2 %0, %1, %2, %0;" : "+l"(d) : "l"(a), "l"(b));
}
__device__ __forceinline__ uint32_t cvtpack(float lo, float hi) {
    uint32_t r;
    asm("cvt.rn.f16x2.f32 %0, %1, %2;" : "=r"(r) : "f"(hi), "f"(lo));
    return r;
}
__device__ __forceinline__ uint32_t smem_u32(const void* p) {
    uint32_t a;
    asm("{ .reg .u64 t; cvta.to.shared.u64 t, %1; cvt.u32.u64 %0, t; }"
        : "=r"(a) : "l"(p));
    return a;
}
__device__ __forceinline__ void ldsm4(uint32_t (&r)[4], uint32_t addr) {
    asm volatile("ldmatrix.sync.aligned.m8n8.x4.shared.b16 {%0,%1,%2,%3}, [%4];"
        : "=r"(r[0]), "=r"(r[1]), "=r"(r[2]), "=r"(r[3]) : "r"(addr));
}
__device__ __forceinline__ void mma16816(float (&d)[4], const uint32_t (&a)[4],
                                         uint32_t b0, uint32_t b1) {
    asm volatile(
        "mma.sync.aligned.m16n8k16.row.col.f32.f16.f16.f32 "
        "{%0,%1,%2,%3}, {%4,%5,%6,%7}, {%8,%9}, {%0,%1,%2,%3};"
        : "+f"(d[0]), "+f"(d[1]), "+f"(d[2]), "+f"(d[3])
        : "r"(a[0]), "r"(a[1]), "r"(a[2]), "r"(a[3]), "r"(b0), "r"(b1));
}
#define CP16(dst, src) \
    asm volatile("cp.async.ca.shared.global [%0], [%1], 16;" :: "r"(dst), "l"(src))
#define CP_COMMIT() asm volatile("cp.async.commit_group;" ::: "memory")
#define CP_WAIT0()  asm volatile("cp.async.wait_group 0;" ::: "memory")
#define CP_WAIT1()  asm volatile("cp.async.wait_group 1;" ::: "memory")

// ============ prep: W2 -> fp16 [kk][n][k] swizzled; W1 -> dup pairs ============
__global__ void prep_kernel(const float* __restrict__ W2,
                            const float* __restrict__ W1) {
    int i = blockIdx.x * 256 + threadIdx.x;
    if (i < 9 * 128 * 64) {
        int ci = i & 63, n = (i >> 6) & 127, kk = i >> 13;
        float v = W2[(kk * 64 + ci) * 128 + n];
        int j = ci >> 3;
        g_w2t[kk * 8192 + n * 64 + ((j ^ (n & 7)) << 3) + (ci & 7)] = __float2half_rn(v);
    } else if (i < 9 * 128 * 64 + 27 * 64) {
        int j = i - 9 * 128 * 64;
        float v = W1[j];
        g_w1d[j] = pk2(v, v);
    }
}

// ============ image staging (producer, 4 warps): 19 rows x 69 cols x 3 ch ============
__device__ __forceinline__ void stage_img(
    float* s_img, const int* __restrict__ img, int gy0, int ix0, int pw, int lane)
{
    for (int row = pw; row < 19; row += 4) {
        const int gy = gy0 + row;
        const bool yok = gy < IMG;
        const int* src = img + ((size_t)gy * IMG + ix0) * 3;
        float* rb = s_img + row * IROW;
#pragma unroll
        for (int xi0 = 0; xi0 < 96; xi0 += 32) {
            const int xi = xi0 + lane;
            if (xi >= 69) break;
            const bool ok = yok && (ix0 + xi) < IMG;
#pragma unroll
            for (int c = 0; c < 3; c++) {
                float v = ok ? (float)src[3 * xi + c] * (1.f / 255.f) : 0.f;
                float* rbc = rb + c * IPLANE;
                if (xi & 1) {
                    rbc[36 + (xi >> 1)] = v;
                } else {
                    const int h = xi >> 1;
                    rbc[h] = v;
                    if (h >= 1) rbc[72 + h - 1] = v;    // S[j] = E[j+1]
                }
            }
        }
    }
}

// ============ conv1 store for pair p into buffer inb ============
__device__ __forceinline__ void conv1_store(
    char* inb, int r, int p, int lane, u64 a0, u64 a1, int cx0, bool rowok)
{
    float e0, o0, e1, o1;
    upk2(a0, e0, o0);
    upk2(a1, e1, o1);
    uint32_t he = 0;
    if (rowok && (cx0 + 2 * p) < 1152)
        he = cvtpack(fmaxf(e0, 0.f), fmaxf(e1, 0.f));
    const int pr = r * 17 + p;
    *(uint32_t*)(inb + pr * 128 +
                 (((lane >> 2) ^ (pr & 7)) << 4) + ((lane & 3) << 2)) = he;
    if (p < 16) {
        uint32_t ho = 0;
        if (rowok && (cx0 + 2 * p + 1) < 1152)
            ho = cvtpack(fmaxf(o0, 0.f), fmaxf(o1, 0.f));
        const int po = r * 16 + p;
        *(uint32_t*)(inb + INO_REL + po * 128 +
                     (((lane >> 2) ^ (po & 7)) << 4) + ((lane & 3) << 2)) = ho;
    }
}

// ============ conv1 full row (17 pairs, single weight pass) ============
__device__ __forceinline__ void conv1_row17(
    char* inb, const float* rowbase, const u64* s_w1, int r, int lane,
    u64 bias0, u64 bias1, int cx0, bool rowok)
{
    u64 a0[17], a1[17];
#pragma unroll
    for (int i = 0; i < 17; i++) { a0[i] = bias0; a1[i] = bias1; }

#pragma unroll
    for (int ky = 0; ky < 3; ky++)
#pragma unroll
    for (int ci = 0; ci < 3; ci++) {
        const ulonglong2* vp =
            (const ulonglong2*)(rowbase + ci * IPLANE + ky * IROW);
#pragma unroll
        for (int kx = 0; kx < 3; kx++) {
            const int off = (kx == 0 ? 0 : (kx == 1 ? 9 : 18));
            const ulonglong2 wq = *(const ulonglong2*)(
                s_w1 + ((ky * 3 + kx) * 3 + ci) * 64 + 2 * lane);
            ulonglong2 Q[5];
#pragma unroll
            for (int k = 0; k < 5; k++) Q[k] = vp[off + k];
#pragma unroll
            for (int p = 0; p < 10; p++) {
                const u64 in = (p & 1) ? Q[p >> 1].y : Q[p >> 1].x;
                fma2(a0[p], in, wq.x);
                fma2(a1[p], in, wq.y);
            }
#pragma unroll
            for (int k = 0; k < 4; k++) Q[k] = vp[off + 5 + k];
#pragma unroll
            for (int p = 10; p < 17; p++) {
                const u64 in = (p & 1) ? Q[(p >> 1) - 5].y : Q[(p >> 1) - 5].x;
                fma2(a0[p], in, wq.x);
                fma2(a1[p], in, wq.y);
            }
        }
    }
#pragma unroll
    for (int p = 0; p < 17; p++)
        conv1_store(inb, r, p, lane, a0[p], a1[p], cx0, rowok);
}

// ============ conv1 half row (split row 16) ============
template <int P0, int NP>
__device__ __forceinline__ void conv1_half(
    char* inb, const float* rowbase, const u64* s_w1, int r, int lane,
    u64 bias0, u64 bias1, int cx0, bool rowok)
{
    u64 a0[NP], a1[NP];
#pragma unroll
    for (int i = 0; i < NP; i++) { a0[i] = bias0; a1[i] = bias1; }

#pragma unroll
    for (int ky = 0; ky < 3; ky++)
#pragma unroll
    for (int ci = 0; ci < 3; ci++) {
        const ulonglong2* vp =
            (const ulonglong2*)(rowbase + ci * IPLANE + ky * IROW);
#pragma unroll
        for (int kx = 0; kx < 3; kx++) {
            const int off = (kx == 0 ? 0 : (kx == 1 ? 9 : 18)) + (P0 >> 1);
            ulonglong2 Q[5];
#pragma unroll
            for (int k = 0; k < 5; k++) Q[k] = vp[off + k];
            const ulonglong2 wq = *(const ulonglong2*)(
                s_w1 + ((ky * 3 + kx) * 3 + ci) * 64 + 2 * lane);
#pragma unroll
            for (int i = 0; i < NP; i++) {
                const int p = P0 + i;
                const u64 in = (p & 1) ? Q[(p >> 1) - (P0 >> 1)].y
                                       : Q[(p >> 1) - (P0 >> 1)].x;
                fma2(a0[i], in, wq.x);
                fma2(a1[i], in, wq.y);
            }
        }
    }
#pragma unroll
    for (int i = 0; i < NP; i++)
        conv1_store(inb, r, P0 + i, lane, a0[i], a1[i], cx0, rowok);
}

#define NTILES 9

// ============ fused pipeline kernel: 256 thr, 1 CTA/SM ============
__global__ __launch_bounds__(256, 1) void fused_kernel(
    const int* __restrict__ img,
    const float* __restrict__ b1,
    const float* __restrict__ b2,
    float* __restrict__ out)
{
    extern __shared__ __align__(128) char smem[];
    const uint32_t sb = smem_u32(smem);
    const int t = threadIdx.x, lane = t & 31, wid = t >> 5;
    const int bx = blockIdx.x, by = blockIdx.y;

    if (wid >= 4) {
        // ================= PRODUCER (warps 4-7) =================
        const int pw = wid - 4;
        const int pt = t - 128;

        for (int i = pt; i < 864; i += 128)
            CP16(sb + W1_OFF + i * 16, (const char*)g_w1d + i * 16);
        CP_COMMIT();

        const u64* s_w1 = (const u64*)(smem + W1_OFF);
        const u64 bias0 = pk2(__ldg(b1 + 2 * lane), __ldg(b1 + 2 * lane));
        const u64 bias1 = pk2(__ldg(b1 + 2 * lane + 1), __ldg(b1 + 2 * lane + 1));
        float* s_img = (float*)(smem + IMG_OFF);
        const int iy0 = 32 * by, cy0 = 16 * by;

        for (int ti = 0; ti < NTILES; ti++) {
            const int pb = ti & 1;
            const int tx = NTILES * bx + ti;
            const int ix0 = 64 * tx, cx0 = 32 * tx;
            char* inb = smem + pb * BUFSZ;

            stage_img(s_img, img, iy0, ix0, pw, lane);
            if (ti == 0) CP_WAIT0();
            BAR_SYNC(PBAR_ID, 128);
            if (ti >= 2) BAR_SYNC(EMPTY_ID(pb), 256);

            conv1_row17(inb, s_img + 2 * pw * IROW, s_w1, pw, lane,
                        bias0, bias1, cx0, (cy0 + pw) < 1152);
            conv1_row17(inb, s_img + 2 * (pw + 4) * IROW, s_w1, pw + 4, lane,
                        bias0, bias1, cx0, (cy0 + pw + 4) < 1152);
            BAR_SYNC(PBAR_ID, 128);

            stage_img(s_img, img, iy0 + 16, ix0, pw, lane);
            BAR_SYNC(PBAR_ID, 128);

            conv1_row17(inb, s_img + 2 * pw * IROW, s_w1, 8 + pw, lane,
                        bias0, bias1, cx0, (cy0 + 8 + pw) < 1152);
            conv1_row17(inb, s_img + (2 * pw + 8) * IROW, s_w1, 12 + pw, lane,
                        bias0, bias1, cx0, (cy0 + 12 + pw) < 1152);
            const bool ok16 = (cy0 + 16) < 1152;
            if (pw == 0)
                conv1_half<0, 9>(inb, s_img + 16 * IROW, s_w1, 16, lane,
                                 bias0, bias1, cx0, ok16);
            if (pw == 1)
                conv1_half<9, 8>(inb, s_img + 16 * IROW, s_w1, 16, lane,
                                 bias0, bias1, cx0, ok16);
            MEMBAR_CTA();
            BAR_ARRIVE(FULL_ID(pb), 256);
        }
    } else {
        // ================= CONSUMER (warps 0-3) =================
        const int wm = wid >> 1, wn = wid & 1;
        const int xa = lane & 15;
        const int ca = lane >> 4;
        const int nb = (lane & 7) + ((lane >> 4) << 3);
        const int cb2 = (lane >> 3) & 1;
        const int eB = lane & 7;
        uint32_t qB[4];
#pragma unroll
        for (int g = 0; g < 4; g++)
            qB[g] = sb + B_OFF + (uint32_t)(64 * wn + 16 * g + nb) * 128;
        const int y0g = 8 * by;

        for (int ti = 0; ti < NTILES; ti++) {
            const int cbuf = ti & 1;
            const int tx = NTILES * bx + ti;

            // stage B0 (overlaps producer conv1 / own full-wait)
            for (int i = t; i < 1024; i += 128)
                CP16(sb + B_OFF + i * 16, (const char*)g_w2t + i * 16);
            CP_COMMIT();

            BAR_SYNC(FULL_ID(cbuf), 256);

            float d[4][8][4];
#pragma unroll
            for (int mt = 0; mt < 4; mt++)
#pragma unroll
                for (int j = 0; j < 8; j++)
#pragma unroll
                    for (int q = 0; q < 4; q++) d[mt][j][q] = 0.f;

            const uint32_t sIN = sb + cbuf * BUFSZ;

            for (int kk = 0; kk < 9; kk++) {
                if (kk < 8) {
                    const char* src = (const char*)(g_w2t + (kk + 1) * 8192);
                    uint32_t dstb = sb + B_OFF + (uint32_t)(((kk + 1) & 1) << 14);
                    for (int i = t; i < 1024; i += 128)
                        CP16(dstb + i * 16, src + i * 16);
                    CP_COMMIT();
                    CP_WAIT1();
                } else {
                    CP_WAIT0();
                }
                BAR_SYNC(CBAR_ID, 128);

                const int ky = kk / 3, kx = kk - ky * 3;
                uint32_t arel; int W, xoff;
                if (kx == 1) { arel = INO_REL; W = 16; xoff = 0; }
                else         { arel = 0;       W = 17; xoff = kx >> 1; }
                uint32_t q[4]; int e[4];
#pragma unroll
                for (int mt = 0; mt < 4; mt++) {
                    const int u = (8 * wm + 2 * mt + ky) * W + xa + xoff;
                    q[mt] = sIN + arel + (uint32_t)u * 128;
                    e[mt] = u & 7;
                }
                const uint32_t bufo = (uint32_t)((kk & 1) << 14);

#pragma unroll
                for (int s4 = 0; s4 < 4; s4++) {
                    const int cA = 2 * s4 + ca;
                    uint32_t A[4][4];
#pragma unroll
                    for (int mt = 0; mt < 4; mt++)
                        ldsm4(A[mt], q[mt] + (uint32_t)((cA ^ e[mt]) << 4));
                    const uint32_t xb =
                        (uint32_t)((((2 * s4 + cb2) ^ eB) << 4)) + bufo;
#pragma unroll
                    for (int g = 0; g < 4; g++) {
                        uint32_t B[4];
                        ldsm4(B, qB[g] + xb);
#pragma unroll
                        for (int mt = 0; mt < 4; mt++) {
                            mma16816(d[mt][2 * g],     A[mt], B[0], B[1]);
                            mma16816(d[mt][2 * g + 1], A[mt], B[2], B[3]);
                        }
                    }
                }
            }
            BAR_SYNC(CBAR_ID, 128);   // all consumer reads of IN[cbuf] done

            // epilogue: transpose into IN[cbuf] region, bias+ReLU, NCHW f4
            float* s_out = (float*)(smem + cbuf * BUFSZ);   // [128 co][132]
            const int g = lane >> 2;
#pragma unroll
            for (int mt = 0; mt < 4; mt++)
#pragma unroll
                for (int tj = 0; tj < 8; tj++)
#pragma unroll
                    for (int rp = 0; rp < 2; rp++) {
                        const int m = (4 * wm + mt) * 16 + g + 8 * rp;
                        const int n = 64 * wn + 8 * tj + 2 * (lane & 3);
                        s_out[n * 132 + m]       = d[mt][tj][2 * rp];
                        s_out[(n + 1) * 132 + m] = d[mt][tj][2 * rp + 1];
                    }
            BAR_SYNC(CBAR_ID, 128);

            const int x0g = 16 * tx;
            for (int u = t; u < 4096; u += 128) {
                const int co = u >> 5, j = u & 31;
                const int y = j >> 2, x = 4 * (j & 3);
                const float bb = __ldg(b2 + co);
                float4 v = *(float4*)(s_out + co * 132 + 4 * j);
                v.x = fmaxf(v.x + bb, 0.f);
                v.y = fmaxf(v.y + bb, 0.f);
                v.z = fmaxf(v.z + bb, 0.f);
                v.w = fmaxf(v.w + bb, 0.f);
                *(float4*)(out + ((size_t)co * H2 + y0g + y) * H2 + x0g + x) = v;
            }
            BAR_ARRIVE(EMPTY_ID(cbuf), 256);
        }
    }
}

// ======================= launch =======================
extern "C" void kernel_launch(void* const* d_in, const int* in_sizes, int n_in,
                              void* d_out, int out_size)
{
    const int*   img = (const int*)d_in[0];
    const float* W1  = (const float*)d_in[1];
    const float* b1  = (const float*)d_in[2];
    const float* W2  = (const float*)d_in[3];
    const float* b2  = (const float*)d_in[4];
    float* out = (float*)d_out;

    cudaFuncSetAttribute(fused_kernel,
                         cudaFuncAttributeMaxDynamicSharedMemorySize, SMEMT);

    prep_kernel<<<(9 * 128 * 64 + 27 * 64 + 255) / 256, 256>>>(W2, W1);
    fused_kernel<<<dim3(4, 72), 256, SMEMT>>>(img, b1, b2, out);
}

// round 15
// speedup vs baseline: 1.3472x; 1.3472x over previous
#include <cuda_runtime.h>
#include <cuda_fp16.h>
#include <cstdint>

// Warp-specialized pipeline v4: 512 threads. Producer warps 8-15 run conv1
// (FFMA2) into double-buffered smem fp16 tiles; consumer warps 0-7 run conv2
// (HMMA, m32n64/warp) + epilogue. 9 tiles per CTA, 1 CTA/SM, named barriers.
// v3 fix: producer-internal barrier at loop top (s_img WAR race).
// v4 fix: consumer B double-buffer reordered to R8-proven scheme — stage at
// top, MMA, then CP_WAIT0 + CBAR at END of each kk (closes B-buffer WAR race).

#define IMG 2304
#define H2  576

typedef unsigned long long u64;

__device__ __half g_w2t[9 * 128 * 64];   // [kk][n=co][k=ci] fp16, SW128-baked
__device__ u64    g_w1d[27 * 64];        // conv1 weights dup-packed (w,w)

// smem map (bytes)
#define BUFSZ   71808                // one IN tile: E 36992 + O 34816
#define INO_REL 36992
#define B_OFF   143616               // B dbuf 2 x 16384
#define W1_OFF  176384               // 13824
#define IMG_OFF 190208               // 3ch x 19rows x 108 f32 = 24624
#define SMEMT   214832
#define IROW    108                  // E[0..35] | O@36 | S@72
#define IPLANE  (19 * IROW)

// named barrier ids
#define FULL_ID(b)  (1 + (b))        // producer arrives, consumer syncs (512)
#define EMPTY_ID(b) (3 + (b))        // consumer arrives, producer syncs (512)
#define PBAR_ID 5                    // producer-internal (256)
#define CBAR_ID 6                    // consumer-internal (256)
#define BAR_SYNC(id, cnt) \
    asm volatile("bar.sync %0, %1;" :: "r"(id), "r"(cnt) : "memory")
#define BAR_ARRIVE(id, cnt) \
    asm volatile("bar.arrive %0, %1;" :: "r"(id), "r"(cnt) : "memory")
#define MEMBAR_CTA() asm volatile("membar.cta;" ::: "memory")

// ---------------- helpers ----------------
__device__ __forceinline__ u64 pk2(float x, float y) {
    u64 r; asm("mov.b64 %0, {%1, %2};" : "=l"(r) : "f"(x), "f"(y)); return r;
}
__device__ __forceinline__ void upk2(u64 v, float& x, float& y) {
    asm("mov.b64 {%0, %1}, %2;" : "=f"(x), "=f"(y) : "l"(v));
}
__device__ __forceinline__ void fma2(u64& d, u64 a, u64 b) {
    asm("fma.rn.f32x2 %0, %1, %2, %0;" : "+l"(d) : "l"(a), "l"(b));
}
__device__ __forceinline__ uint32_t cvtpack(float lo, float hi) {
    uint32_t r;
    asm("cvt.rn.f16x2.f32 %0, %1, %2;" : "=r"(r) : "f"(hi), "f"(lo));
    return r;
}
__device__ __forceinline__ uint32_t smem_u32(const void* p) {
    uint32_t a;
    asm("{ .reg .u64 t; cvta.to.shared.u64 t, %1; cvt.u32.u64 %0, t; }"
        : "=r"(a) : "l"(p));
    return a;
}
__device__ __forceinline__ void ldsm4(uint32_t (&r)[4], uint32_t addr) {
    asm volatile("ldmatrix.sync.aligned.m8n8.x4.shared.b16 {%0,%1,%2,%3}, [%4];"
        : "=r"(r[0]), "=r"(r[1]), "=r"(r[2]), "=r"(r[3]) : "r"(addr));
}
__device__ __forceinline__ void mma16816(float (&d)[4], const uint32_t (&a)[4],
                                         uint32_t b0, uint32_t b1) {
    asm volatile(
        "mma.sync.aligned.m16n8k16.row.col.f32.f16.f16.f32 "
        "{%0,%1,%2,%3}, {%4,%5,%6,%7}, {%8,%9}, {%0,%1,%2,%3};"
        : "+f"(d[0]), "+f"(d[1]), "+f"(d[2]), "+f"(d[3])
        : "r"(a[0]), "r"(a[1]), "r"(a[2]), "r"(a[3]), "r"(b0), "r"(b1));
}
#define CP16(dst, src) \
    asm volatile("cp.async.ca.shared.global [%0], [%1], 16;" :: "r"(dst), "l"(src))
#define CP_COMMIT() asm volatile("cp.async.commit_group;" ::: "memory")
#define CP_WAIT0()  asm volatile("cp.async.wait_group 0;" ::: "memory")

// ============ prep: W2 -> fp16 [kk][n][k] swizzled; W1 -> dup pairs ============
__global__ void prep_kernel(const float* __restrict__ W2,
                            const float* __restrict__ W1) {
    int i = blockIdx.x * 256 + threadIdx.x;
    if (i < 9 * 128 * 64) {
        int ci = i & 63, n = (i >> 6) & 127, kk = i >> 13;
        float v = W2[(kk * 64 + ci) * 128 + n];
        int j = ci >> 3;
        g_w2t[kk * 8192 + n * 64 + ((j ^ (n & 7)) << 3) + (ci & 7)] = __float2half_rn(v);
    } else if (i < 9 * 128 * 64 + 27 * 64) {
        int j = i - 9 * 128 * 64;
        float v = W1[j];
        g_w1d[j] = pk2(v, v);
    }
}

// ============ image staging (8 producer warps): 19 rows x 69 cols x 3 ch ============
__device__ __forceinline__ void stage_img(
    float* s_img, const int* __restrict__ img, int gy0, int ix0, int pw, int lane)
{
    for (int row = pw; row < 19; row += 8) {
        const int gy = gy0 + row;
        const bool yok = gy < IMG;
        const int* src = img + ((size_t)gy * IMG + ix0) * 3;
        float* rb = s_img + row * IROW;
#pragma unroll
        for (int xi0 = 0; xi0 < 96; xi0 += 32) {
            const int xi = xi0 + lane;
            if (xi >= 69) break;
            const bool ok = yok && (ix0 + xi) < IMG;
#pragma unroll
            for (int c = 0; c < 3; c++) {
                float v = ok ? (float)src[3 * xi + c] * (1.f / 255.f) : 0.f;
                float* rbc = rb + c * IPLANE;
                if (xi & 1) {
                    rbc[36 + (xi >> 1)] = v;
                } else {
                    const int h = xi >> 1;
                    rbc[h] = v;
                    if (h >= 1) rbc[72 + h - 1] = v;    // S[j] = E[j+1]
                }
            }
        }
    }
}

// ============ conv1 store for pair p into buffer inb ============
__device__ __forceinline__ void conv1_store(
    char* inb, int r, int p, int lane, u64 a0, u64 a1, int cx0, bool rowok)
{
    float e0, o0, e1, o1;
    upk2(a0, e0, o0);
    upk2(a1, e1, o1);
    uint32_t he = 0;
    if (rowok && (cx0 + 2 * p) < 1152)
        he = cvtpack(fmaxf(e0, 0.f), fmaxf(e1, 0.f));
    const int pr = r * 17 + p;
    *(uint32_t*)(inb + pr * 128 +
                 (((lane >> 2) ^ (pr & 7)) << 4) + ((lane & 3) << 2)) = he;
    if (p < 16) {
        uint32_t ho = 0;
        if (rowok && (cx0 + 2 * p + 1) < 1152)
            ho = cvtpack(fmaxf(o0, 0.f), fmaxf(o1, 0.f));
        const int po = r * 16 + p;
        *(uint32_t*)(inb + INO_REL + po * 128 +
                     (((lane >> 2) ^ (po & 7)) << 4) + ((lane & 3) << 2)) = ho;
    }
}

// ============ conv1 full row (17 pairs, single weight pass) ============
__device__ __forceinline__ void conv1_row17(
    char* inb, const float* rowbase, const u64* s_w1, int r, int lane,
    u64 bias0, u64 bias1, int cx0, bool rowok)
{
    u64 a0[17], a1[17];
#pragma unroll
    for (int i = 0; i < 17; i++) { a0[i] = bias0; a1[i] = bias1; }

#pragma unroll
    for (int ky = 0; ky < 3; ky++)
#pragma unroll
    for (int ci = 0; ci < 3; ci++) {
        const ulonglong2* vp =
            (const ulonglong2*)(rowbase + ci * IPLANE + ky * IROW);
#pragma unroll
        for (int kx = 0; kx < 3; kx++) {
            const int off = (kx == 0 ? 0 : (kx == 1 ? 9 : 18));
            const ulonglong2 wq = *(const ulonglong2*)(
                s_w1 + ((ky * 3 + kx) * 3 + ci) * 64 + 2 * lane);
            ulonglong2 Q[5];
#pragma unroll
            for (int k = 0; k < 5; k++) Q[k] = vp[off + k];
#pragma unroll
            for (int p = 0; p < 10; p++) {
                const u64 in = (p & 1) ? Q[p >> 1].y : Q[p >> 1].x;
                fma2(a0[p], in, wq.x);
                fma2(a1[p], in, wq.y);
            }
#pragma unroll
            for (int k = 0; k < 4; k++) Q[k] = vp[off + 5 + k];
#pragma unroll
            for (int p = 10; p < 17; p++) {
                const u64 in = (p & 1) ? Q[(p >> 1) - 5].y : Q[(p >> 1) - 5].x;
                fma2(a0[p], in, wq.x);
                fma2(a1[p], in, wq.y);
            }
        }
    }
#pragma unroll
    for (int p = 0; p < 17; p++)
        conv1_store(inb, r, p, lane, a0[p], a1[p], cx0, rowok);
}

// ============ conv1 half row (split row 16) ============
template <int P0, int NP>
__device__ __forceinline__ void conv1_half(
    char* inb, const float* rowbase, const u64* s_w1, int r, int lane,
    u64 bias0, u64 bias1, int cx0, bool rowok)
{
    u64 a0[NP], a1[NP];
#pragma unroll
    for (int i = 0; i < NP; i++) { a0[i] = bias0; a1[i] = bias1; }

#pragma unroll
    for (int ky = 0; ky < 3; ky++)
#pragma unroll
    for (int ci = 0; ci < 3; ci++) {
        const ulonglong2* vp =
            (const ulonglong2*)(rowbase + ci * IPLANE + ky * IROW);
#pragma unroll
        for (int kx = 0; kx < 3; kx++) {
            const int off = (kx == 0 ? 0 : (kx == 1 ? 9 : 18)) + (P0 >> 1);
            ulonglong2 Q[5];
#pragma unroll
            for (int k = 0; k < 5; k++) Q[k] = vp[off + k];
            const ulonglong2 wq = *(const ulonglong2*)(
                s_w1 + ((ky * 3 + kx) * 3 + ci) * 64 + 2 * lane);
#pragma unroll
            for (int i = 0; i < NP; i++) {
                const int p = P0 + i;
                const u64 in = (p & 1) ? Q[(p >> 1) - (P0 >> 1)].y
                                       : Q[(p >> 1) - (P0 >> 1)].x;
                fma2(a0[i], in, wq.x);
                fma2(a1[i], in, wq.y);
            }
        }
    }
#pragma unroll
    for (int i = 0; i < NP; i++)
        conv1_store(inb, r, P0 + i, lane, a0[i], a1[i], cx0, rowok);
}

#define NTILES 9

// ============ fused pipeline kernel: 512 thr (8 prod + 8 cons warps) ============
__global__ __launch_bounds__(512, 1) void fused_kernel(
    const int* __restrict__ img,
    const float* __restrict__ b1,
    const float* __restrict__ b2,
    float* __restrict__ out)
{
    extern __shared__ __align__(128) char smem[];
    const uint32_t sb = smem_u32(smem);
    const int t = threadIdx.x, lane = t & 31, wid = t >> 5;
    const int bx = blockIdx.x, by = blockIdx.y;

    if (wid >= 8) {
        // ================= PRODUCER (warps 8-15) =================
        const int pw = wid - 8;
        const int pt = t - 256;

        for (int i = pt; i < 864; i += 256)
            CP16(sb + W1_OFF + i * 16, (const char*)g_w1d + i * 16);
        CP_COMMIT();

        const u64* s_w1 = (const u64*)(smem + W1_OFF);
        const u64 bias0 = pk2(__ldg(b1 + 2 * lane), __ldg(b1 + 2 * lane));
        const u64 bias1 = pk2(__ldg(b1 + 2 * lane + 1), __ldg(b1 + 2 * lane + 1));
        float* s_img = (float*)(smem + IMG_OFF);
        const int iy0 = 32 * by, cy0 = 16 * by;

        for (int ti = 0; ti < NTILES; ti++) {
            const int pb = ti & 1;
            const int tx = NTILES * bx + ti;
            const int ix0 = 64 * tx, cx0 = 32 * tx;
            char* inb = smem + pb * BUFSZ;

            // v3: close s_img read(chunk-B conv1, prev tile)/write race.
            if (ti > 0) BAR_SYNC(PBAR_ID, 256);

            // chunk A: img rows 0..18 -> conv1 rows 0..7
            stage_img(s_img, img, iy0, ix0, pw, lane);
            if (ti == 0) CP_WAIT0();
            BAR_SYNC(PBAR_ID, 256);
            if (ti >= 2) BAR_SYNC(EMPTY_ID(pb), 512);

            conv1_row17(inb, s_img + 2 * pw * IROW, s_w1, pw, lane,
                        bias0, bias1, cx0, (cy0 + pw) < 1152);
            BAR_SYNC(PBAR_ID, 256);

            // chunk B: img rows 16..34 -> conv1 rows 8..16
            stage_img(s_img, img, iy0 + 16, ix0, pw, lane);
            BAR_SYNC(PBAR_ID, 256);

            conv1_row17(inb, s_img + (2 * pw) * IROW, s_w1, 8 + pw, lane,
                        bias0, bias1, cx0, (cy0 + 8 + pw) < 1152);
            const bool ok16 = (cy0 + 16) < 1152;
            if (pw == 6)
                conv1_half<0, 9>(inb, s_img + 16 * IROW, s_w1, 16, lane,
                                 bias0, bias1, cx0, ok16);
            if (pw == 7)
                conv1_half<9, 8>(inb, s_img + 16 * IROW, s_w1, 16, lane,
                                 bias0, bias1, cx0, ok16);
            MEMBAR_CTA();
            BAR_ARRIVE(FULL_ID(pb), 512);
        }
    } else {
        // ================= CONSUMER (warps 0-7) =================
        const int wm = wid >> 1, wn = wid & 1;
        const int xa = lane & 15;
        const int ca = lane >> 4;
        const int nb = (lane & 7) + ((lane >> 4) << 3);
        const int cb2 = (lane >> 3) & 1;
        const int eB = lane & 7;
        uint32_t qB[4];
#pragma unroll
        for (int g = 0; g < 4; g++)
            qB[g] = sb + B_OFF + (uint32_t)(64 * wn + 16 * g + nb) * 128;
        const int y0g = 8 * by;

        for (int ti = 0; ti < NTILES; ti++) {
            const int cbuf = ti & 1;
            const int tx = NTILES * bx + ti;

            // stage B0 into buffer 0 (overlaps the FULL wait). Safe vs the
            // previous tile's kk=8 reads of buffer 0: those completed before
            // the epilogue CBAR syncs this thread already passed.
            for (int i = t; i < 1024; i += 256)
                CP16(sb + B_OFF + i * 16, (const char*)g_w2t + i * 16);
            CP_COMMIT();

            BAR_SYNC(FULL_ID(cbuf), 512);
            CP_WAIT0();                 // B0 landed (thread-local)
            BAR_SYNC(CBAR_ID, 256);     // B0 visible to all consumer warps

            float d[2][8][4];
#pragma unroll
            for (int mt = 0; mt < 2; mt++)
#pragma unroll
                for (int j = 0; j < 8; j++)
#pragma unroll
                    for (int q = 0; q < 4; q++) d[mt][j][q] = 0.f;

            const uint32_t sIN = sb + cbuf * BUFSZ;

            for (int kk = 0; kk < 9; kk++) {
                // v4: stage B[kk+1] at TOP. WAR-safe: buffer (kk+1)&1 was
                // last read at kk-1, whose reads finished before the barrier
                // at the END of kk-1 (below), which precedes this point.
                if (kk < 8) {
                    const char* src = (const char*)(g_w2t + (kk + 1) * 8192);
                    uint32_t dstb = sb + B_OFF + (uint32_t)(((kk + 1) & 1) << 14);
                    for (int i = t; i < 1024; i += 256)
                        CP16(dstb + i * 16, src + i * 16);
                    CP_COMMIT();
                }

                const int ky = kk / 3, kx = kk - ky * 3;
                uint32_t arel; int W, xoff;
                if (kx == 1) { arel = INO_REL; W = 16; xoff = 0; }
                else         { arel = 0;       W = 17; xoff = kx >> 1; }
                const int u0 = (4 * wm + ky) * W + xa + xoff;
                const int u1 = (4 * wm + 2 + ky) * W + xa + xoff;
                const uint32_t q0 = sIN + arel + (uint32_t)u0 * 128;
                const uint32_t q1 = sIN + arel + (uint32_t)u1 * 128;
                const int e0 = u0 & 7, e1 = u1 & 7;
                const uint32_t bufo = (uint32_t)((kk & 1) << 14);

#pragma unroll
                for (int s4 = 0; s4 < 4; s4++) {
                    const int cA = 2 * s4 + ca;
                    uint32_t A0[4], A1[4];
                    ldsm4(A0, q0 + (uint32_t)((cA ^ e0) << 4));
                    ldsm4(A1, q1 + (uint32_t)((cA ^ e1) << 4));
                    const uint32_t xb =
                        (uint32_t)((((2 * s4 + cb2) ^ eB) << 4)) + bufo;
#pragma unroll
                    for (int g = 0; g < 4; g++) {
                        uint32_t B[4];
                        ldsm4(B, qB[g] + xb);
                        mma16816(d[0][2 * g],     A0, B[0], B[1]);
                        mma16816(d[0][2 * g + 1], A0, B[2], B[3]);
                        mma16816(d[1][2 * g],     A1, B[0], B[1]);
                        mma16816(d[1][2 * g + 1], A1, B[2], B[3]);
                    }
                }

                // v4: wait for B[kk+1] group + barrier at END of iteration.
                if (kk < 8) CP_WAIT0();
                BAR_SYNC(CBAR_ID, 256);
            }

            // epilogue: transpose into IN[cbuf] region, bias+ReLU, NCHW f4
            float* s_out = (float*)(smem + cbuf * BUFSZ);   // [128 co][132]
            const int g = lane >> 2;
#pragma unroll
            for (int mt = 0; mt < 2; mt++)
#pragma unroll
                for (int tj = 0; tj < 8; tj++)
#pragma unroll
                    for (int rp = 0; rp < 2; rp++) {
                        const int m = (2 * wm + mt) * 16 + g + 8 * rp;
                        const int n = 64 * wn + 8 * tj + 2 * (lane & 3);
                        s_out[n * 132 + m]       = d[mt][tj][2 * rp];
                        s_out[(n + 1) * 132 + m] = d[mt][tj][2 * rp + 1];
                    }
            BAR_SYNC(CBAR_ID, 256);

            const int x0g = 16 * tx;
            for (int u = t; u < 4096; u += 256) {
                const int co = u >> 5, j = u & 31;
                const int y = j >> 2, x = 4 * (j & 3);
                const float bb = __ldg(b2 + co);
                float4 v = *(float4*)(s_out + co * 132 + 4 * j);
                v.x = fmaxf(v.x + bb, 0.f);
                v.y = fmaxf(v.y + bb, 0.f);
                v.z = fmaxf(v.z + bb, 0.f);
                v.w = fmaxf(v.w + bb, 0.f);
                *(float4*)(out + ((size_t)co * H2 + y0g + y) * H2 + x0g + x) = v;
            }
            BAR_ARRIVE(EMPTY_ID(cbuf), 512);
        }
    }
}

// ======================= launch =======================
extern "C" void kernel_launch(void* const* d_in, const int* in_sizes, int n_in,
                              void* d_out, int out_size)
{
    const int*   img = (const int*)d_in[0];
    const float* W1  = (const float*)d_in[1];
    const float* b1  = (const float*)d_in[2];
    const float* W2  = (const float*)d_in[3];
    const float* b2  = (const float*)d_in[4];
    float* out = (float*)d_out;

    cudaFuncSetAttribute(fused_kernel,
                         cudaFuncAttributeMaxDynamicSharedMemorySize, SMEMT);

    prep_kernel<<<(9 * 128 * 64 + 27 * 64 + 255) / 256, 256>>>(W2, W1);
    fused_kernel<<<dim3(4, 72), 512, SMEMT>>>(img, b1, b2, out);
}

// round 16
// speedup vs baseline: 1.4374x; 1.0669x over previous
#include <cuda_runtime.h>
#include <cuda_fp16.h>
#include <cstdint>

// R16: R9 design (all-warps phase-parallel, proven) scaled to M=256 tiles.
// 512 threads, 1 CTA/SM, tile = 8y x 32x conv2 outputs (M=256 px, N=128 co).
// conv1 FFMA2 (fp32) -> smem fp16 SW128 tiles -> conv2 HMMA m16n8k16.
// Full-image equivalence of the tile/crop/stitch pipeline (pad lo=0, hi=1).

#define IMG 2304
#define H2  576

typedef unsigned long long u64;

__device__ __half g_w2t[9 * 128 * 64];   // [kk][n=co][k=ci] fp16, SW128-baked
__device__ u64    g_w1d[27 * 64];        // conv1 weights dup-packed (w,w)

// smem map (bytes)
#define INE_OFF 0                    // 17 rows x 33 E-px = 561 units x 128B
#define INO_OFF 71808                // 17 rows x 32 O-px = 544 units -> 141440
#define B_OFF   141440               // B dbuf 2 x 16384 -> 174208
#define W1_OFF  141440               // overlays B buf0 (dead before conv2)
#define IMG_OFF 174208               // 3ch x 19rows x 204 f32 = 46512
#define SMEMT   220720
#define IROW    204                  // E[0..67] | O@68[0..67] | S@136[0..67]
#define IPLANE  (19 * IROW)

// ---------------- helpers ----------------
__device__ __forceinline__ u64 pk2(float x, float y) {
    u64 r; asm("mov.b64 %0, {%1, %2};" : "=l"(r) : "f"(x), "f"(y)); return r;
}
__device__ __forceinline__ void upk2(u64 v, float& x, float& y) {
    asm("mov.b64 {%0, %1}, %2;" : "=f"(x), "=f"(y) : "l"(v));
}
__device__ __forceinline__ void fma2(u64& d, u64 a, u64 b) {
    asm("fma.rn.f32x2 %0, %1, %2, %0;" : "+l"(d) : "l"(a), "l"(b));
}
__device__ __forceinline__ uint32_t cvtpack(float lo, float hi) {
    uint32_t r;
    asm("cvt.rn.f16x2.f32 %0, %1, %2;" : "=r"(r) : "f"(hi), "f"(lo));
    return r;
}
__device__ __forceinline__ uint32_t smem_u32(const void* p) {
    uint32_t a;
    asm("{ .reg .u64 t; cvta.to.shared.u64 t, %1; cvt.u32.u64 %0, t; }"
        : "=r"(a) : "l"(p));
    return a;
}
__device__ __forceinline__ void ldsm4(uint32_t (&r)[4], uint32_t addr) {
    asm volatile("ldmatrix.sync.aligned.m8n8.x4.shared.b16 {%0,%1,%2,%3}, [%4];"
        : "=r"(r[0]), "=r"(r[1]), "=r"(r[2]), "=r"(r[3]) : "r"(addr));
}
__device__ __forceinline__ void mma16816(float (&d)[4], const uint32_t (&a)[4],
                                         uint32_t b0, uint32_t b1) {
    asm volatile(
        "mma.sync.aligned.m16n8k16.row.col.f32.f16.f16.f32 "
        "{%0,%1,%2,%3}, {%4,%5,%6,%7}, {%8,%9}, {%0,%1,%2,%3};"
        : "+f"(d[0]), "+f"(d[1]), "+f"(d[2]), "+f"(d[3])
        : "r"(a[0]), "r"(a[1]), "r"(a[2]), "r"(a[3]), "r"(b0), "r"(b1));
}
#define CP16(dst, src) \
    asm volatile("cp.async.ca.shared.global [%0], [%1], 16;" :: "r"(dst), "l"(src))
#define CP_COMMIT() asm volatile("cp.async.commit_group;" ::: "memory")
#define CP_WAIT0()  asm volatile("cp.async.wait_group 0;" ::: "memory")
#define CP_WAIT1()  asm volatile("cp.async.wait_group 1;" ::: "memory")

// ============ prep: W2 -> fp16 [kk][n][k] swizzled; W1 -> dup pairs ============
__global__ void prep_kernel(const float* __restrict__ W2,
                            const float* __restrict__ W1) {
    int i = blockIdx.x * 256 + threadIdx.x;
    if (i < 9 * 128 * 64) {
        int ci = i & 63, n = (i >> 6) & 127, kk = i >> 13;
        float v = W2[(kk * 64 + ci) * 128 + n];
        int j = ci >> 3;
        g_w2t[kk * 8192 + n * 64 + ((j ^ (n & 7)) << 3) + (ci & 7)] = __float2half_rn(v);
    } else if (i < 9 * 128 * 64 + 27 * 64) {
        int j = i - 9 * 128 * 64;
        float v = W1[j];
        g_w1d[j] = pk2(v, v);
    }
}

// ============ image staging: 19 rows x 131 cols x 3 ch, parity split E|O|S ============
__device__ __forceinline__ void stage_img(
    float* s_img, const int* __restrict__ img, int gy0, int ix0, int wid, int lane)
{
    for (int row = wid; row < 19; row += 16) {
        const int gy = gy0 + row;
        const bool yok = gy < IMG;
        const int* src = img + ((size_t)gy * IMG + ix0) * 3;
        float* rb = s_img + row * IROW;
#pragma unroll
        for (int xi0 = 0; xi0 < 160; xi0 += 32) {
            const int xi = xi0 + lane;
            if (xi >= 131) break;
            const bool ok = yok && (ix0 + xi) < IMG;
#pragma unroll
            for (int c = 0; c < 3; c++) {
                float v = ok ? (float)src[3 * xi + c] * (1.f / 255.f) : 0.f;
                float* rbc = rb + c * IPLANE;
                if (xi & 1) {
                    rbc[68 + (xi >> 1)] = v;
                } else {
                    const int h = xi >> 1;
                    rbc[h] = v;
                    if (h >= 1) rbc[136 + h - 1] = v;   // S[j] = E[j+1]
                }
            }
        }
    }
}

// ============ conv1 store for pair p (outputs 2p, 2p+1) ============
__device__ __forceinline__ void conv1_store(
    char* inb, int r, int p, int lane, u64 a0, u64 a1, int cx0, bool rowok)
{
    float e0, o0, e1, o1;
    upk2(a0, e0, o0);
    upk2(a1, e1, o1);
    uint32_t he = 0;
    if (rowok && (cx0 + 2 * p) < 1152)
        he = cvtpack(fmaxf(e0, 0.f), fmaxf(e1, 0.f));
    const int pr = r * 33 + p;
    *(uint32_t*)(inb + INE_OFF + pr * 128 +
                 (((lane >> 2) ^ (pr & 7)) << 4) + ((lane & 3) << 2)) = he;
    if (p < 32) {
        uint32_t ho = 0;
        if (rowok && (cx0 + 2 * p + 1) < 1152)
            ho = cvtpack(fmaxf(o0, 0.f), fmaxf(o1, 0.f));
        const int po = r * 32 + p;
        *(uint32_t*)(inb + INO_OFF + po * 128 +
                     (((lane >> 2) ^ (po & 7)) << 4) + ((lane & 3) << 2)) = ho;
    }
}

// ============ conv1 half row: NP pairs from P0; co = 2*lane, 2*lane+1 ============
template <int P0, int NP>
__device__ __forceinline__ void conv1_half(
    char* inb, const float* rowbase, const u64* s_w1, int r, int lane,
    u64 bias0, u64 bias1, int cx0, bool rowok)
{
    constexpr int QB = P0 >> 1;
    constexpr int N1 = 2 * QB + 10 - P0;   // pairs served by first Q batch
    u64 a0[NP], a1[NP];
#pragma unroll
    for (int i = 0; i < NP; i++) { a0[i] = bias0; a1[i] = bias1; }

#pragma unroll
    for (int ky = 0; ky < 3; ky++)
#pragma unroll
    for (int ci = 0; ci < 3; ci++) {
        const ulonglong2* vp =
            (const ulonglong2*)(rowbase + ci * IPLANE + ky * IROW);
#pragma unroll
        for (int kx = 0; kx < 3; kx++) {
            const int off = (kx == 0 ? 0 : (kx == 1 ? 17 : 34)) + QB;
            const ulonglong2 wq = *(const ulonglong2*)(
                s_w1 + ((ky * 3 + kx) * 3 + ci) * 64 + 2 * lane);
            ulonglong2 Q[5];
#pragma unroll
            for (int k = 0; k < 5; k++) Q[k] = vp[off + k];
#pragma unroll
            for (int i = 0; i < NP; i++) {
                if (i < N1) {
                    const int p = P0 + i;
                    const u64 in = (p & 1) ? Q[(p >> 1) - QB].y
                                           : Q[(p >> 1) - QB].x;
                    fma2(a0[i], in, wq.x);
                    fma2(a1[i], in, wq.y);
                }
            }
#pragma unroll
            for (int k = 0; k < 4; k++) Q[k] = vp[off + 5 + k];
#pragma unroll
            for (int i = 0; i < NP; i++) {
                if (i >= N1) {
                    const int p = P0 + i;
                    const u64 in = (p & 1) ? Q[(p >> 1) - QB - 5].y
                                           : Q[(p >> 1) - QB - 5].x;
                    fma2(a0[i], in, wq.x);
                    fma2(a1[i], in, wq.y);
                }
            }
        }
    }
#pragma unroll
    for (int i = 0; i < NP; i++)
        conv1_store(inb, r, P0 + i, lane, a0[i], a1[i], cx0, rowok);
}

__device__ __forceinline__ void conv1_task(
    char* smem, const float* rowbase, const u64* s_w1, int r, int half,
    int lane, u64 bias0, u64 bias1, int cx0, bool rowok)
{
    if (half == 0)
        conv1_half<0, 17>(smem, rowbase, s_w1, r, lane, bias0, bias1, cx0, rowok);
    else
        conv1_half<17, 16>(smem, rowbase, s_w1, r, lane, bias0, bias1, cx0, rowok);
}

// ============ fused kernel: 512 thr, 32x8 conv2-out tile, 1 CTA/SM ============
__global__ __launch_bounds__(512, 1) void fused_kernel(
    const int* __restrict__ img,
    const float* __restrict__ b1,
    const float* __restrict__ b2,
    float* __restrict__ out)
{
    extern __shared__ __align__(128) char smem[];
    const uint32_t sb = smem_u32(smem);
    const int t = threadIdx.x, lane = t & 31, wid = t >> 5;
    const int bx = blockIdx.x, by = blockIdx.y;

    // Prefetch W1 (group 0) and B0 into buf1 (group 1).
    for (int i = t; i < 864; i += 512)
        CP16(sb + W1_OFF + i * 16, (const char*)g_w1d + i * 16);
    CP_COMMIT();
    for (int i = t; i < 1024; i += 512)
        CP16(sb + B_OFF + 16384 + i * 16, (const char*)g_w2t + i * 16);
    CP_COMMIT();

    float* s_img = (float*)(smem + IMG_OFF);
    const int iy0 = 32 * by, ix0 = 128 * bx;
    const int cx0 = 64 * bx, cy0 = 16 * by;

    // ---- chunk A: img rows 0..18 -> conv1 rows 0..7 (16 half-tasks) ----
    stage_img(s_img, img, iy0, ix0, wid, lane);
    CP_WAIT1();                       // W1 landed (B0 still in flight)
    __syncthreads();

    const u64* s_w1 = (const u64*)(smem + W1_OFF);
    const u64 bias0 = pk2(__ldg(b1 + 2 * lane), __ldg(b1 + 2 * lane));
    const u64 bias1 = pk2(__ldg(b1 + 2 * lane + 1), __ldg(b1 + 2 * lane + 1));

    {
        const int r = wid >> 1;
        conv1_task(smem, s_img + 2 * r * IROW, s_w1, r, wid & 1,
                   lane, bias0, bias1, cx0, (cy0 + r) < 1152);
    }
    __syncthreads();

    // ---- chunk B: img rows 16..34 -> conv1 rows 8..16 (18 half-tasks) ----
    stage_img(s_img, img, iy0 + 16, ix0, wid, lane);
    __syncthreads();

    {
        const int r = 8 + (wid >> 1);
        conv1_task(smem, s_img + (2 * r - 16) * IROW, s_w1, r, wid & 1,
                   lane, bias0, bias1, cx0, (cy0 + r) < 1152);
        if (wid < 2) {
            const bool ok16 = (cy0 + 16) < 1152;
            conv1_task(smem, s_img + 16 * IROW, s_w1, 16, wid,
                       lane, bias0, bias1, cx0, ok16);
        }
    }
    __syncthreads();
    CP_WAIT0();        // B0 landed
    __syncthreads();   // B0 visible to all warps

    // ---- conv2 (HMMA): M=256 px (8y x 32x), N=128; warp: y-row wm, n64 wn ----
    float d[2][8][4];
#pragma unroll
    for (int i = 0; i < 2; i++)
#pragma unroll
        for (int j = 0; j < 8; j++)
#pragma unroll
            for (int q = 0; q < 4; q++) d[i][j][q] = 0.f;

    const int wm = wid >> 1, wn = wid & 1;
    const int xa = lane & 15;
    const int ca = lane >> 4;
    const int nb = (lane & 7) + ((lane >> 4) << 3);
    const int cb2 = (lane >> 3) & 1;
    const int eB = lane & 7;
    uint32_t qB[4];
#pragma unroll
    for (int g = 0; g < 4; g++)
        qB[g] = sb + B_OFF + (uint32_t)(64 * wn + 16 * g + nb) * 128;

    for (int kk = 0; kk < 9; kk++) {
        // stage B[kk+1] into buf (kk&1); kk itself reads buf ((kk+1)&1).
        if (kk < 8) {
            const char* src = (const char*)(g_w2t + (kk + 1) * 8192);
            uint32_t dstb = sb + B_OFF + (uint32_t)((kk & 1) << 14);
            for (int i = t; i < 1024; i += 512)
                CP16(dstb + i * 16, src + i * 16);
            CP_COMMIT();
        }
        const int ky = kk / 3, kx = kk - ky * 3;
        uint32_t arel; int W, xoff;
        if (kx == 1) { arel = INO_OFF; W = 32; xoff = 0; }
        else         { arel = INE_OFF; W = 33; xoff = kx >> 1; }
        const int u0 = (2 * wm + ky) * W + xa + xoff;
        const int u1 = u0 + 16;
        const uint32_t q0 = sb + arel + (uint32_t)u0 * 128;
        const uint32_t q1 = sb + arel + (uint32_t)u1 * 128;
        const int e0 = u0 & 7, e1 = u1 & 7;
        const uint32_t bufo = (uint32_t)(((kk + 1) & 1) << 14);

#pragma unroll
        for (int s4 = 0; s4 < 4; s4++) {
            const int cA = 2 * s4 + ca;
            uint32_t A0[4], A1[4];
            ldsm4(A0, q0 + (uint32_t)((cA ^ e0) << 4));
            ldsm4(A1, q1 + (uint32_t)((cA ^ e1) << 4));
            const uint32_t xb = (uint32_t)((((2 * s4 + cb2) ^ eB) << 4)) + bufo;
#pragma unroll
            for (int g = 0; g < 4; g++) {
                uint32_t B[4];
                ldsm4(B, qB[g] + xb);
                mma16816(d[0][2 * g],     A0, B[0], B[1]);
                mma16816(d[0][2 * g + 1], A0, B[2], B[3]);
                mma16816(d[1][2 * g],     A1, B[0], B[1]);
                mma16816(d[1][2 * g + 1], A1, B[2], B[3]);
            }
        }
        if (kk < 8) CP_WAIT0();
        __syncthreads();
    }

    // ---- epilogue: transpose via smem [128 co][268], bias+ReLU, NCHW f4 ----
    float* s_out = (float*)smem;
    const int g = lane >> 2;
#pragma unroll
    for (int ti = 0; ti < 2; ti++)
#pragma unroll
        for (int tj = 0; tj < 8; tj++)
#pragma unroll
            for (int rp = 0; rp < 2; rp++) {
                const int m = wm * 32 + 16 * ti + g + 8 * rp;
                const int n = 64 * wn + 8 * tj + 2 * (lane & 3);
                s_out[n * 268 + m]       = d[ti][tj][2 * rp];
                s_out[(n + 1) * 268 + m] = d[ti][tj][2 * rp + 1];
            }
    __syncthreads();

    const int x0g = 32 * bx, y0g = 8 * by;
    for (int u = t; u < 8192; u += 512) {
        const int co = u >> 6, j = u & 63;
        const int y = j >> 3, x = 4 * (j & 7);
        const float bb = __ldg(b2 + co);
        float4 v = *(float4*)(s_out + co * 268 + y * 32 + x);
        v.x = fmaxf(v.x + bb, 0.f);
        v.y = fmaxf(v.y + bb, 0.f);
        v.z = fmaxf(v.z + bb, 0.f);
        v.w = fmaxf(v.w + bb, 0.f);
        *(float4*)(out + ((size_t)co * H2 + y0g + y) * H2 + x0g + x) = v;
    }
}

// ======================= launch =======================
extern "C" void kernel_launch(void* const* d_in, const int* in_sizes, int n_in,
                              void* d_out, int out_size)
{
    const int*   img = (const int*)d_in[0];
    const float* W1  = (const float*)d_in[1];
    const float* b1  = (const float*)d_in[2];
    const float* W2  = (const float*)d_in[3];
    const float* b2  = (const float*)d_in[4];
    float* out = (float*)d_out;

    cudaFuncSetAttribute(fused_kernel,
                         cudaFuncAttributeMaxDynamicSharedMemorySize, SMEMT);

    prep_kernel<<<(9 * 128 * 64 + 27 * 64 + 255) / 256, 256>>>(W2, W1);
    fused_kernel<<<dim3(18, 72), 512, SMEMT>>>(img, b1, b2, out);
}

// round 17
// speedup vs baseline: 1.6295x; 1.1337x over previous
#include <cuda_runtime.h>
#include <cuda_fp16.h>
#include <cstdint>

// R17 = R9 (best: 346.6us) + depth-2 register pipeline in conv2 inner loop.
// Fused conv1(FFMA2)+conv2(HMMA m16n8k16). CTA tile 16x8 conv2 outputs
// (M=128 px, N=128 co), 256 threads, 2 CTAs/SM.

#define IMG 2304
#define H2  576

typedef unsigned long long u64;

__device__ __half g_w2t[9 * 128 * 64];   // [kk][n=co][k=ci] fp16, SW128-baked
__device__ u64    g_w1d[27 * 64];        // conv1 weights dup-packed (w,w)

// smem map (bytes)
#define INE_OFF 0                    // 17 rows x 17 E-px = 289 units x 128B
#define INO_OFF 36992                // 17 rows x 16 O-px = 272 units x 128B
#define OVL_OFF 71808
#define B_OFF   OVL_OFF              // conv2: B dbuf 2 x 16384
#define IMG_OFF OVL_OFF              // conv1: 3ch x 19rows x 108 f32 = 24624
#define W1_OFF  (OVL_OFF + 24624)    // conv1: 27*64 u64 = 13824 -> end 110256
#define SMEMT   110256
#define IROW    108                  // E[0..35] | O@36 | S@72
#define IPLANE  (19 * IROW)

// ---------------- helpers ----------------
__device__ __forceinline__ u64 pk2(float x, float y) {
    u64 r; asm("mov.b64 %0, {%1, %2};" : "=l"(r) : "f"(x), "f"(y)); return r;
}
__device__ __forceinline__ void upk2(u64 v, float& x, float& y) {
    asm("mov.b64 {%0, %1}, %2;" : "=f"(x), "=f"(y) : "l"(v));
}
__device__ __forceinline__ void fma2(u64& d, u64 a, u64 b) {
    asm("fma.rn.f32x2 %0, %1, %2, %0;" : "+l"(d) : "l"(a), "l"(b));
}
__device__ __forceinline__ uint32_t cvtpack(float lo, float hi) {
    uint32_t r;
    asm("cvt.rn.f16x2.f32 %0, %1, %2;" : "=r"(r) : "f"(hi), "f"(lo));
    return r;
}
__device__ __forceinline__ uint32_t smem_u32(const void* p) {
    uint32_t a;
    asm("{ .reg .u64 t; cvta.to.shared.u64 t, %1; cvt.u32.u64 %0, t; }"
        : "=r"(a) : "l"(p));
    return a;
}
__device__ __forceinline__ void ldsm4(uint32_t (&r)[4], uint32_t addr) {
    asm volatile("ldmatrix.sync.aligned.m8n8.x4.shared.b16 {%0,%1,%2,%3}, [%4];"
        : "=r"(r[0]), "=r"(r[1]), "=r"(r[2]), "=r"(r[3]) : "r"(addr));
}
__device__ __forceinline__ void mma16816(float (&d)[4], const uint32_t (&a)[4],
                                         uint32_t b0, uint32_t b1) {
    asm volatile(
        "mma.sync.aligned.m16n8k16.row.col.f32.f16.f16.f32 "
        "{%0,%1,%2,%3}, {%4,%5,%6,%7}, {%8,%9}, {%0,%1,%2,%3};"
        : "+f"(d[0]), "+f"(d[1]), "+f"(d[2]), "+f"(d[3])
        : "r"(a[0]), "r"(a[1]), "r"(a[2]), "r"(a[3]), "r"(b0), "r"(b1));
}
#define CP16(dst, src) \
    asm volatile("cp.async.ca.shared.global [%0], [%1], 16;" :: "r"(dst), "l"(src))
#define CP_COMMIT() asm volatile("cp.async.commit_group;" ::: "memory")
#define CP_WAIT0()  asm volatile("cp.async.wait_group 0;" ::: "memory")

// ============ prep: W2 -> fp16 [kk][n][k] swizzled; W1 -> dup pairs ============
__global__ void prep_kernel(const float* __restrict__ W2,
                            const float* __restrict__ W1) {
    int i = blockIdx.x * 256 + threadIdx.x;
    if (i < 9 * 128 * 64) {
        int ci = i & 63, n = (i >> 6) & 127, kk = i >> 13;
        float v = W2[(kk * 64 + ci) * 128 + n];
        int j = ci >> 3;
        g_w2t[kk * 8192 + n * 64 + ((j ^ (n & 7)) << 3) + (ci & 7)] = __float2half_rn(v);
    } else if (i < 9 * 128 * 64 + 27 * 64) {
        int j = i - 9 * 128 * 64;
        float v = W1[j];
        g_w1d[j] = pk2(v, v);
    }
}

// ============ image staging: 19 rows x 69 cols x 3 ch, parity split E|O|S ============
__device__ __forceinline__ void stage_img(
    float* s_img, const int* __restrict__ img, int gy0, int ix0, int wid, int lane)
{
    for (int row = wid; row < 19; row += 8) {
        const int gy = gy0 + row;
        const bool yok = gy < IMG;
        const int* src = img + ((size_t)gy * IMG + ix0) * 3;
        float* rb = s_img + row * IROW;
#pragma unroll
        for (int xi0 = 0; xi0 < 96; xi0 += 32) {
            const int xi = xi0 + lane;
            if (xi >= 69) break;
            const bool ok = yok && (ix0 + xi) < IMG;
#pragma unroll
            for (int c = 0; c < 3; c++) {
                float v = ok ? (float)src[3 * xi + c] * (1.f / 255.f) : 0.f;
                float* rbc = rb + c * IPLANE;
                if (xi & 1) {
                    rbc[36 + (xi >> 1)] = v;
                } else {
                    const int h = xi >> 1;
                    rbc[h] = v;
                    if (h >= 1) rbc[72 + h - 1] = v;    // S[j] = E[j+1]
                }
            }
        }
    }
}

// ============ conv1 store for pair p ============
__device__ __forceinline__ void conv1_store(
    char* smem, int r, int p, int lane, u64 a0, u64 a1, int cx0, bool rowok)
{
    float e0, o0, e1, o1;
    upk2(a0, e0, o0);
    upk2(a1, e1, o1);
    uint32_t he = 0;
    if (rowok && (cx0 + 2 * p) < 1152)
        he = cvtpack(fmaxf(e0, 0.f), fmaxf(e1, 0.f));
    const int pr = r * 17 + p;
    *(uint32_t*)(smem + INE_OFF + pr * 128 +
                 (((lane >> 2) ^ (pr & 7)) << 4) + ((lane & 3) << 2)) = he;
    if (p < 16) {
        uint32_t ho = 0;
        if (rowok && (cx0 + 2 * p + 1) < 1152)
            ho = cvtpack(fmaxf(o0, 0.f), fmaxf(o1, 0.f));
        const int po = r * 16 + p;
        *(uint32_t*)(smem + INO_OFF + po * 128 +
                     (((lane >> 2) ^ (po & 7)) << 4) + ((lane & 3) << 2)) = ho;
    }
}

// ============ conv1 full row (17 pairs, single weight pass) ============
__device__ __forceinline__ void conv1_row17(
    char* smem, const float* rowbase, const u64* s_w1, int r, int lane,
    u64 bias0, u64 bias1, int cx0, bool rowok)
{
    u64 a0[17], a1[17];
#pragma unroll
    for (int i = 0; i < 17; i++) { a0[i] = bias0; a1[i] = bias1; }

#pragma unroll
    for (int ky = 0; ky < 3; ky++)
#pragma unroll
    for (int ci = 0; ci < 3; ci++) {
        const ulonglong2* vp =
            (const ulonglong2*)(rowbase + ci * IPLANE + ky * IROW);
#pragma unroll
        for (int kx = 0; kx < 3; kx++) {
            const int off = (kx == 0 ? 0 : (kx == 1 ? 9 : 18));
            const ulonglong2 wq = *(const ulonglong2*)(
                s_w1 + ((ky * 3 + kx) * 3 + ci) * 64 + 2 * lane);
            ulonglong2 Q[5];
#pragma unroll
            for (int k = 0; k < 5; k++) Q[k] = vp[off + k];
#pragma unroll
            for (int p = 0; p < 10; p++) {
                const u64 in = (p & 1) ? Q[p >> 1].y : Q[p >> 1].x;
                fma2(a0[p], in, wq.x);
                fma2(a1[p], in, wq.y);
            }
#pragma unroll
            for (int k = 0; k < 4; k++) Q[k] = vp[off + 5 + k];
#pragma unroll
            for (int p = 10; p < 17; p++) {
                const u64 in = (p & 1) ? Q[(p >> 1) - 5].y : Q[(p >> 1) - 5].x;
                fma2(a0[p], in, wq.x);
                fma2(a1[p], in, wq.y);
            }
        }
    }
#pragma unroll
    for (int p = 0; p < 17; p++)
        conv1_store(smem, r, p, lane, a0[p], a1[p], cx0, rowok);
}

// ============ conv1 half row (for the split row 16) ============
template <int P0, int NP>
__device__ __forceinline__ void conv1_half(
    char* smem, const float* rowbase, const u64* s_w1, int r, int lane,
    u64 bias0, u64 bias1, int cx0, bool rowok)
{
    u64 a0[NP], a1[NP];
#pragma unroll
    for (int i = 0; i < NP; i++) { a0[i] = bias0; a1[i] = bias1; }

#pragma unroll
    for (int ky = 0; ky < 3; ky++)
#pragma unroll
    for (int ci = 0; ci < 3; ci++) {
        const ulonglong2* vp =
            (const ulonglong2*)(rowbase + ci * IPLANE + ky * IROW);
#pragma unroll
        for (int kx = 0; kx < 3; kx++) {
            const int off = (kx == 0 ? 0 : (kx == 1 ? 9 : 18)) + (P0 >> 1);
            ulonglong2 Q[5];
#pragma unroll
            for (int k = 0; k < 5; k++) Q[k] = vp[off + k];
            const ulonglong2 wq = *(const ulonglong2*)(
                s_w1 + ((ky * 3 + kx) * 3 + ci) * 64 + 2 * lane);
#pragma unroll
            for (int i = 0; i < NP; i++) {
                const int p = P0 + i;
                const u64 in = (p & 1) ? Q[(p >> 1) - (P0 >> 1)].y
                                       : Q[(p >> 1) - (P0 >> 1)].x;
                fma2(a0[i], in, wq.x);
                fma2(a1[i], in, wq.y);
            }
        }
    }
#pragma unroll
    for (int i = 0; i < NP; i++)
        conv1_store(smem, r, P0 + i, lane, a0[i], a1[i], cx0, rowok);
}

// ============ fused kernel: 256 thr, 16x8 conv2-out tile, 2 CTAs/SM ============
__global__ __launch_bounds__(256, 2) void fused_kernel(
    const int* __restrict__ img,
    const float* __restrict__ b1,
    const float* __restrict__ b2,
    float* __restrict__ out)
{
    extern __shared__ __align__(128) char smem[];
    const uint32_t sb = smem_u32(smem);
    const int t = threadIdx.x, lane = t & 31, wid = t >> 5;
    const int bx = blockIdx.x, by = blockIdx.y;

    // W1 dup pairs -> smem (above the image chunk region).
    for (int i = t; i < 864; i += 256)
        CP16(sb + W1_OFF + i * 16, (const char*)g_w1d + i * 16);
    CP_COMMIT();

    float* s_img = (float*)(smem + IMG_OFF);
    const int iy0 = 32 * by, ix0 = 64 * bx;

    // ---- chunk A: img rows 0..18 -> conv1 rows 0..7 ----
    stage_img(s_img, img, iy0, ix0, wid, lane);
    CP_WAIT0();
    __syncthreads();

    const u64* s_w1 = (const u64*)(smem + W1_OFF);
    const u64 bias0 = pk2(__ldg(b1 + 2 * lane), __ldg(b1 + 2 * lane));
    const u64 bias1 = pk2(__ldg(b1 + 2 * lane + 1), __ldg(b1 + 2 * lane + 1));
    const int cx0 = 32 * bx, cy0 = 16 * by;

    {
        const int r = wid;
        conv1_row17(smem, s_img + 2 * r * IROW, s_w1, r, lane,
                    bias0, bias1, cx0, (cy0 + r) < 1152);
    }
    __syncthreads();

    // ---- chunk B: img rows 16..34 -> conv1 rows 8..16 ----
    stage_img(s_img, img, iy0 + 16, ix0, wid, lane);
    __syncthreads();

    {
        const int r = 8 + wid;
        conv1_row17(smem, s_img + (2 * r - 16) * IROW, s_w1, r, lane,
                    bias0, bias1, cx0, (cy0 + r) < 1152);
        const float* rb16 = s_img + 16 * IROW;
        const bool ok16 = (cy0 + 16) < 1152;
        if (wid == 6)
            conv1_half<0, 9>(smem, rb16, s_w1, 16, lane, bias0, bias1, cx0, ok16);
        if (wid == 7)
            conv1_half<9, 8>(smem, rb16, s_w1, 16, lane, bias0, bias1, cx0, ok16);
    }
    __syncthreads();   // conv1 done; img/W1 region dead -> B dbuf may use it

    // Stage B0.
    for (int i = t; i < 1024; i += 256)
        CP16(sb + B_OFF + i * 16, (const char*)g_w2t + i * 16);
    CP_COMMIT();
    CP_WAIT0();
    __syncthreads();

    // ---- conv2 (HMMA): M=128 px (8y x 16x), N=128 co; warp = m32 x n64 ----
    float d[2][8][4];
#pragma unroll
    for (int i = 0; i < 2; i++)
#pragma unroll
        for (int j = 0; j < 8; j++)
#pragma unroll
            for (int q = 0; q < 4; q++) d[i][j][q] = 0.f;

    const int wm = wid >> 1, wn = wid & 1;
    const int xa = lane & 15;
    const int ca = lane >> 4;
    const int nb = (lane & 7) + ((lane >> 4) << 3);
    const int cb2 = (lane >> 3) & 1;
    const int eB = lane & 7;
    uint32_t qB[4];
#pragma unroll
    for (int g = 0; g < 4; g++)
        qB[g] = sb + B_OFF + (uint32_t)(64 * wn + 16 * g + nb) * 128;

    for (int kk = 0; kk < 9; kk++) {
        if (kk < 8) {
            const char* src = (const char*)(g_w2t + (kk + 1) * 8192);
            uint32_t dstb = sb + B_OFF + (uint32_t)(((kk + 1) & 1) << 14);
            for (int i = t; i < 1024; i += 256)
                CP16(dstb + i * 16, src + i * 16);
            CP_COMMIT();
        }
        const int ky = kk / 3, kx = kk - ky * 3;
        uint32_t arr; int W, xoff;
        if (kx == 1) { arr = INO_OFF; W = 16; xoff = 0; }
        else         { arr = INE_OFF; W = 17; xoff = kx >> 1; }
        const int u0 = (4 * wm + ky) * W + xa + xoff;
        const int u1 = (4 * wm + 2 + ky) * W + xa + xoff;
        const uint32_t q0 = sb + arr + (uint32_t)u0 * 128;
        const uint32_t q1 = sb + arr + (uint32_t)u1 * 128;
        const int e0 = u0 & 7, e1 = u1 & 7;
        const uint32_t bufo = (uint32_t)((kk & 1) << 14);

        // R17: depth-2 register pipeline over s4 — ldsm for s4+1 issued
        // BEFORE the 16 mmas of s4, hiding LDS latency under tensor work.
        uint32_t Af[2][2][4];
        uint32_t Bf[2][4][4];
        {
            ldsm4(Af[0][0], q0 + (uint32_t)((ca ^ e0) << 4));
            ldsm4(Af[0][1], q1 + (uint32_t)((ca ^ e1) << 4));
            const uint32_t xb = (uint32_t)(((cb2 ^ eB) << 4)) + bufo;
#pragma unroll
            for (int g = 0; g < 4; g++) ldsm4(Bf[0][g], qB[g] + xb);
        }
#pragma unroll
        for (int s4 = 0; s4 < 4; s4++) {
            const int bk = s4 & 1, nbk = bk ^ 1;
            if (s4 < 3) {
                const int cA = 2 * (s4 + 1) + ca;
                ldsm4(Af[nbk][0], q0 + (uint32_t)((cA ^ e0) << 4));
                ldsm4(Af[nbk][1], q1 + (uint32_t)((cA ^ e1) << 4));
                const uint32_t xb =
                    (uint32_t)((((2 * (s4 + 1) + cb2) ^ eB) << 4)) + bufo;
#pragma unroll
                for (int g = 0; g < 4; g++) ldsm4(Bf[nbk][g], qB[g] + xb);
            }
#pragma unroll
            for (int g = 0; g < 4; g++) {
                mma16816(d[0][2 * g],     Af[bk][0], Bf[bk][g][0], Bf[bk][g][1]);
                mma16816(d[0][2 * g + 1], Af[bk][0], Bf[bk][g][2], Bf[bk][g][3]);
                mma16816(d[1][2 * g],     Af[bk][1], Bf[bk][g][0], Bf[bk][g][1]);
                mma16816(d[1][2 * g + 1], Af[bk][1], Bf[bk][g][2], Bf[bk][g][3]);
            }
        }
        if (kk < 8) CP_WAIT0();
        __syncthreads();
    }

    // ---- epilogue: transpose via smem [128 co][132], bias+ReLU, NCHW f4 ----
    float* s_out = (float*)smem;
    const int g = lane >> 2;
#pragma unroll
    for (int ti = 0; ti < 2; ti++)
#pragma unroll
        for (int tj = 0; tj < 8; tj++)
#pragma unroll
            for (int rp = 0; rp < 2; rp++) {
                const int m = (2 * wm + ti) * 16 + g + 8 * rp;
                const int n = 64 * wn + 8 * tj + 2 * (lane & 3);
                s_out[n * 132 + m]       = d[ti][tj][2 * rp];
                s_out[(n + 1) * 132 + m] = d[ti][tj][2 * rp + 1];
            }
    __syncthreads();

    const int x0g = 16 * bx, y0g = 8 * by;
    for (int u = t; u < 4096; u += 256) {
        const int co = u >> 5, j = u & 31;
        const int y = j >> 2, x = 4 * (j & 3);
        const float bb = __ldg(b2 + co);
        float4 v = *(float4*)(s_out + co * 132 + 4 * j);
        v.x = fmaxf(v.x + bb, 0.f);
        v.y = fmaxf(v.y + bb, 0.f);
        v.z = fmaxf(v.z + bb, 0.f);
        v.w = fmaxf(v.w + bb, 0.f);
        *(float4*)(out + ((size_t)co * H2 + y0g + y) * H2 + x0g + x) = v;
    }
}

// ======================= launch =======================
extern "C" void kernel_launch(void* const* d_in, const int* in_sizes, int n_in,
                              void* d_out, int out_size)
{
    const int*   img = (const int*)d_in[0];
    const float* W1  = (const float*)d_in[1];
    const float* b1  = (const float*)d_in[2];
    const float* W2  = (const float*)d_in[3];
    const float* b2  = (const float*)d_in[4];
    float* out = (float*)d_out;

    cudaFuncSetAttribute(fused_kernel,
                         cudaFuncAttributeMaxDynamicSharedMemorySize, SMEMT);

    prep_kernel<<<(9 * 128 * 64 + 27 * 64 + 255) / 256, 256>>>(W2, W1);
    fused_kernel<<<dim3(36, 72), 256, SMEMT>>>(img, b1, b2, out);
}